// round 7
// baseline (speedup 1.0000x reference)
#include <cuda_runtime.h>

// L1LossWithPenalty — 4-stage cp.async pipeline (prefetch distance 3).
// out = (1/N) * sum_i [ sum_c |pred[i,c]-tgt[i,c]| ] * penalty[argmax pred_i, argmax tgt_i]
// N = 1048576, C = 27.  226 MB streamed -> HBM-bound.
//
// R6 vs R5 (47.1us, DRAM 61.2%, occ 22.2%):
//  - pipeline depth 2 -> 4: each tile's copies get ~3 iteration periods to
//    land; each block keeps 3 tiles (83KB) continuously in flight -> DRAM
//    demand de-burstified.
//  - smem 110.6KB/block -> 2 blocks/SM, grid = 296 persistent blocks.

#define C        27
#define ROWS     128
#define THREADS  128
#define TILE_F   (ROWS * C)          // 3456 floats per array per tile
#define TILE_4   (TILE_F / 4)        // 864 float4
#define FULLIT   (TILE_4 / THREADS)  // 6
#define REM      (TILE_4 - FULLIT * THREADS) // 96
#define STAGES   4
#define STAGE_F  (2 * TILE_F)        // pred+tgt per stage
#define SMEM_BYTES (STAGES * STAGE_F * 4)   // 110592 B
#define GRID     296                 // 2 blocks/SM on 148 SMs

__device__ double   g_acc;    // zero at module load; self-reset each run
__device__ unsigned g_count;

__device__ __forceinline__ void cp16(float* smem_dst, const float4* gmem_src) {
    unsigned saddr = (unsigned)__cvta_generic_to_shared(smem_dst);
    asm volatile("cp.async.cg.shared.global [%0], [%1], 16;\n"
                 :: "r"(saddr), "l"(gmem_src) : "memory");
}
__device__ __forceinline__ void cp_commit() {
    asm volatile("cp.async.commit_group;\n" ::: "memory");
}
__device__ __forceinline__ void cp_wait3() {
    asm volatile("cp.async.wait_group 3;\n" ::: "memory");
}

__global__ __launch_bounds__(THREADS)
void l1pen_kernel(const float* __restrict__ pred,
                  const float* __restrict__ tgt,
                  const float* __restrict__ pen,
                  int nrows,
                  float* __restrict__ out)
{
    extern __shared__ float dynsm[];   // [STAGES][2][TILE_F]
    __shared__ float s_warp[THREADS / 32];

    const int tid    = threadIdx.x;
    const int ntiles = (nrows + ROWS - 1) / ROWS;
    const int stride = gridDim.x;

    // ---- issue copies for one tile into stage s ----
    auto issue_tile = [&](int tile, int s) {
        float* sp = dynsm + s * STAGE_F;
        float* st = sp + TILE_F;
        const long base = (long)tile * TILE_F;
        const int rows = min(ROWS, nrows - tile * ROWS);
        if (rows == ROWS) {
            const float4* p4 = (const float4*)(pred + base);
            const float4* t4 = (const float4*)(tgt  + base);
            #pragma unroll
            for (int k = 0; k < FULLIT; k++) {
                cp16(sp + (tid + k * THREADS) * 4, p4 + tid + k * THREADS);
                cp16(st + (tid + k * THREADS) * 4, t4 + tid + k * THREADS);
            }
            if (tid < REM) {
                cp16(sp + (FULLIT * THREADS + tid) * 4, p4 + FULLIT * THREADS + tid);
                cp16(st + (FULLIT * THREADS + tid) * 4, t4 + FULLIT * THREADS + tid);
            }
        } else {
            // ragged last tile (dead for N=1M = 8192 full tiles)
            const int nflt = rows * C;
            for (int i = tid; i < nflt; i += THREADS) {
                sp[i] = pred[base + i];
                st[i] = tgt [base + i];
            }
        }
    };

    float acc = 0.0f;

    // Prologue: prefetch up to 3 tiles ahead (one commit group each).
    #pragma unroll
    for (int p = 0; p < STAGES - 1; p++) {
        int t = blockIdx.x + p * stride;
        if (t < ntiles)
            issue_tile(t, p);
        cp_commit();
    }

    int it = 0;
    for (int tile = blockIdx.x; tile < ntiles; tile += stride, it++) {
        const int ahead = tile + (STAGES - 1) * stride;
        if (ahead < ntiles)
            issue_tile(ahead, (it + STAGES - 1) % STAGES);
        cp_commit();          // uniform one group per iteration
        cp_wait3();           // oldest group (this tile) complete
        __syncthreads();

        // ---- compute from stage it % STAGES ----
        const int s = it % STAGES;
        const int rows = min(ROWS, nrows - tile * ROWS);
        if (tid < rows) {
            const float* __restrict__ pr = dynsm + s * STAGE_F + tid * C;
            const float* __restrict__ tr = pr + TILE_F;
            float l1 = 0.0f;
            float pmax = pr[0], tmax = tr[0];
            int   pidx = 0,     tidx = 0;
            #pragma unroll
            for (int c = 0; c < C; c++) {
                float a = pr[c];
                float b = tr[c];
                l1 += fabsf(a - b);
                if (a > pmax) { pmax = a; pidx = c; }  // strict > == jnp.argmax ties
                if (b > tmax) { tmax = b; tidx = c; }
            }
            acc += l1 * __ldg(&pen[pidx * C + tidx]);
        }
        __syncthreads();      // stage free before it's re-filled (3 iters later)
    }

    // ---- one reduction + one atomic per block ----
    #pragma unroll
    for (int off = 16; off > 0; off >>= 1)
        acc += __shfl_down_sync(0xffffffffu, acc, off);
    if ((tid & 31) == 0)
        s_warp[tid >> 5] = acc;
    __syncthreads();

    if (tid == 0) {
        float s = 0.0f;
        #pragma unroll
        for (int w = 0; w < THREADS / 32; w++)
            s += s_warp[w];

        atomicAdd(&g_acc, (double)s);
        __threadfence();
        unsigned done = atomicAdd(&g_count, 1u) + 1u;
        if (done == gridDim.x) {
            __threadfence();
            double v = atomicAdd(&g_acc, 0.0);
            *out = (float)(v / (double)nrows);
            g_acc = 0.0;          // self-reset for next graph replay
            __threadfence();
            g_count = 0u;
        }
    }
}

extern "C" void kernel_launch(void* const* d_in, const int* in_sizes, int n_in,
                              void* d_out, int out_size)
{
    int pen_i = -1;
    for (int i = 0; i < n_in; i++)
        if (in_sizes[i] == C * C) { pen_i = i; break; }
    int big[2], nb = 0;
    for (int i = 0; i < n_in && nb < 2; i++)
        if (i != pen_i) big[nb++] = i;

    const float* pred = (const float*)d_in[big[0]];
    const float* tgt  = (const float*)d_in[big[1]];
    const float* pen  = (const float*)d_in[pen_i];

    const int nrows = in_sizes[big[0]] / C;

    cudaFuncSetAttribute(l1pen_kernel,
                         cudaFuncAttributeMaxDynamicSharedMemorySize, SMEM_BYTES);

    l1pen_kernel<<<GRID, THREADS, SMEM_BYTES>>>(pred, tgt, pen, nrows,
                                                (float*)d_out);
}

// round 8
// speedup vs baseline: 1.1099x; 1.1099x over previous
#include <cuda_runtime.h>
#include <cstdint>

// L1LossWithPenalty — warp-specialized TMA-bulk pipeline.
// out = (1/N) * sum_i [ sum_c |pred[i,c]-tgt[i,c]| ] * penalty[argmax pred_i, argmax tgt_i]
// N = 1048576, C = 27.  226 MB streamed -> HBM-bound.
//
// R7 vs R6 (47.2us, DRAM 58.8%):  R5/R6 showed depth changes are NEUTRAL ->
// the limiter is bursty request issue serialized with compute in the same
// warps. Now: 1 producer warp issues cp.async.bulk (2 instrs/tile) into a
// 4-stage mbarrier ring, decoupled from 4 consumer warps. No __syncthreads
// in the steady-state loop; TMA engine keeps DRAM demand continuous.

#define C        27
#define ROWS     128                  // rows per tile (= consumer threads)
#define CONS     128                  // consumer threads (4 warps)
#define THREADS  160                  // + 1 producer warp
#define TILE_F   (ROWS * C)           // 3456 floats
#define TILE_B   (TILE_F * 4)         // 13824 bytes per array per tile
#define STAGE_F  (2 * TILE_F)
#define STAGES   4
#define SMEM_BYTES (STAGES * STAGE_F * 4)   // 110592 B
#define GRID     296

__device__ double   g_acc;
__device__ unsigned g_count;

// ---- mbarrier / TMA-bulk primitives ----
#define MBARRIER_INIT(addr, cnt) \
    asm volatile("mbarrier.init.shared.b64 [%0], %1;" :: "r"(addr), "r"(cnt) : "memory")

#define MBARRIER_ARRIVE(addr) \
    asm volatile("mbarrier.arrive.shared.b64 _, [%0];" :: "r"(addr) : "memory")

#define MBARRIER_EXPECT_TX(addr, bytes) \
    asm volatile("mbarrier.arrive.expect_tx.shared.b64 _, [%0], %1;" \
                 :: "r"(addr), "r"(bytes) : "memory")

#define MBARRIER_WAIT_PARITY(addr, parity) do {                                   \
    uint32_t _mbar = (addr); uint32_t _par = (parity); uint32_t _done;            \
    asm volatile("{\n\t.reg .pred p;\n\t"                                         \
        "mbarrier.try_wait.parity.acquire.cta.shared::cta.b64 p, [%1], %2;\n\t"   \
        "selp.b32 %0, 1, 0, p;\n\t}"                                              \
        : "=r"(_done) : "r"(_mbar), "r"(_par) : "memory");                        \
    if (!_done) {                                                                 \
        asm volatile("{\n\t.reg .pred P1;\n\t"                                    \
            "WL_%=:\n\t"                                                          \
            "mbarrier.try_wait.parity.acquire.cta.shared::cta.b64 P1, [%0], %1, 0x989680;\n\t" \
            "@P1 bra.uni WD_%=;\n\t"                                              \
            "bra.uni WL_%=;\n\t"                                                  \
            "WD_%=:\n\t}" :: "r"(_mbar), "r"(_par) : "memory");                   \
    }                                                                             \
} while (0)

#define MBARRIER_WAIT_PARITY_RELAXED(addr, parity) do {                           \
    uint32_t _mbar = (addr); uint32_t _par = (parity); uint32_t _done;            \
    asm volatile("{\n\t.reg .pred p;\n\t"                                         \
        "mbarrier.try_wait.parity.relaxed.cta.shared::cta.b64 p, [%1], %2, 0x989680;\n\t" \
        "selp.b32 %0, 1, 0, p;\n\t}"                                              \
        : "=r"(_done) : "r"(_mbar), "r"(_par) : "memory");                        \
    if (!_done) {                                                                 \
        asm volatile("{\n\t.reg .pred P1;\n\t"                                    \
            "WL_%=:\n\t"                                                          \
            "mbarrier.try_wait.parity.relaxed.cta.shared::cta.b64 P1, [%0], %1, 0x989680;\n\t" \
            "@P1 bra.uni WD_%=;\n\t"                                              \
            "bra.uni WL_%=;\n\t"                                                  \
            "WD_%=:\n\t}" :: "r"(_mbar), "r"(_par) : "memory");                   \
    }                                                                             \
} while (0)

__device__ __forceinline__ void tma_bulk_g2s(uint32_t smem_dst, const void* gmem_src,
                                             uint32_t bytes, uint32_t mbar) {
    asm volatile(
        "cp.async.bulk.shared::cluster.global.mbarrier::complete_tx::bytes "
        "[%0], [%1], %2, [%3];"
        :: "r"(smem_dst), "l"(gmem_src), "r"(bytes), "r"(mbar) : "memory");
}

__global__ __launch_bounds__(THREADS)
void l1pen_kernel(const float* __restrict__ pred,
                  const float* __restrict__ tgt,
                  const float* __restrict__ pen,
                  int nrows,
                  float* __restrict__ out)
{
    extern __shared__ float dynsm[];            // [STAGES][2][TILE_F]
    __shared__ alignas(16) unsigned long long mbars[2 * STAGES]; // full/empty pairs
    __shared__ float s_warp[CONS / 32];

    const int tid    = threadIdx.x;
    const int wid    = tid >> 5;
    const int nfull  = nrows / ROWS;            // full tiles (8192 for N=1M)
    const int ntiles = (nrows + ROWS - 1) / ROWS;
    const int stride = gridDim.x;

    const uint32_t mb0 = (uint32_t)__cvta_generic_to_shared(mbars);
    auto full_addr  = [&](int s) { return mb0 + (uint32_t)(2 * s) * 8u; };
    auto empty_addr = [&](int s) { return mb0 + (uint32_t)(2 * s + 1) * 8u; };

    if (tid == 0) {
        #pragma unroll
        for (int s = 0; s < STAGES; s++) {
            MBARRIER_INIT(full_addr(s), 1u);     // producer's expect_tx arrive
            MBARRIER_INIT(empty_addr(s), (uint32_t)CONS);  // all consumers arrive
        }
    }
    __syncthreads();

    float acc = 0.0f;

    if (wid == 4) {
        // -------- producer warp (lane 0 only) --------
        if ((tid & 31) == 0) {
            int s = 0, phase = 1;                // phase=1: first empty-wait passes
            for (int tile = blockIdx.x; tile < nfull; tile += stride) {
                MBARRIER_WAIT_PARITY_RELAXED(empty_addr(s), phase);
                MBARRIER_EXPECT_TX(full_addr(s), 2u * TILE_B);
                const uint32_t dst =
                    (uint32_t)__cvta_generic_to_shared(dynsm + s * STAGE_F);
                tma_bulk_g2s(dst,          pred + (long)tile * TILE_F, TILE_B, full_addr(s));
                tma_bulk_g2s(dst + TILE_B, tgt  + (long)tile * TILE_F, TILE_B, full_addr(s));
                if (++s == STAGES) { s = 0; phase ^= 1; }
            }
        }
    } else {
        // -------- consumer warps (128 threads, 1 row each per tile) --------
        int s = 0, phase = 0;
        for (int tile = blockIdx.x; tile < ntiles; tile += stride) {
            if (tile < nfull) {
                MBARRIER_WAIT_PARITY(full_addr(s), phase);   // acquire: TMA data visible
                const float* __restrict__ pr = dynsm + s * STAGE_F + tid * C;
                const float* __restrict__ tr = pr + TILE_F;
                float l1 = 0.0f;
                float pmax = pr[0], tmax = tr[0];
                int   pidx = 0,     tidx = 0;
                #pragma unroll
                for (int c = 0; c < C; c++) {
                    float a = pr[c];
                    float b = tr[c];
                    l1 += fabsf(a - b);
                    if (a > pmax) { pmax = a; pidx = c; }   // strict > == jnp.argmax ties
                    if (b > tmax) { tmax = b; tidx = c; }
                }
                acc += l1 * __ldg(&pen[pidx * C + tidx]);
                MBARRIER_ARRIVE(empty_addr(s));              // release: reads done
                if (++s == STAGES) { s = 0; phase ^= 1; }
            } else {
                // ragged last tile (dead for N=1M): direct global reads
                const int rows = nrows - nfull * ROWS;
                if (tid < rows) {
                    const long base = (long)(nfull * ROWS + tid) * C;
                    float l1 = 0.0f;
                    float pmax = pred[base], tmax = tgt[base];
                    int   pidx = 0,          tidx = 0;
                    #pragma unroll
                    for (int c = 0; c < C; c++) {
                        float a = pred[base + c];
                        float b = tgt [base + c];
                        l1 += fabsf(a - b);
                        if (a > pmax) { pmax = a; pidx = c; }
                        if (b > tmax) { tmax = b; tidx = c; }
                    }
                    acc += l1 * __ldg(&pen[pidx * C + tidx]);
                }
            }
        }

        // warp reduce (consumer warps only)
        #pragma unroll
        for (int off = 16; off > 0; off >>= 1)
            acc += __shfl_down_sync(0xffffffffu, acc, off);
        if ((tid & 31) == 0)
            s_warp[wid] = acc;
    }

    __syncthreads();   // all 5 warps: consumers done writing s_warp

    if (tid == 0) {
        float s = 0.0f;
        #pragma unroll
        for (int w = 0; w < CONS / 32; w++)
            s += s_warp[w];

        atomicAdd(&g_acc, (double)s);
        __threadfence();
        unsigned done = atomicAdd(&g_count, 1u) + 1u;
        if (done == gridDim.x) {
            __threadfence();
            double v = atomicAdd(&g_acc, 0.0);
            *out = (float)(v / (double)nrows);
            g_acc = 0.0;              // self-reset for next graph replay
            __threadfence();
            g_count = 0u;
        }
    }
}

extern "C" void kernel_launch(void* const* d_in, const int* in_sizes, int n_in,
                              void* d_out, int out_size)
{
    int pen_i = -1;
    for (int i = 0; i < n_in; i++)
        if (in_sizes[i] == C * C) { pen_i = i; break; }
    int big[2], nb = 0;
    for (int i = 0; i < n_in && nb < 2; i++)
        if (i != pen_i) big[nb++] = i;

    const float* pred = (const float*)d_in[big[0]];
    const float* tgt  = (const float*)d_in[big[1]];
    const float* pen  = (const float*)d_in[pen_i];

    const int nrows = in_sizes[big[0]] / C;

    cudaFuncSetAttribute(l1pen_kernel,
                         cudaFuncAttributeMaxDynamicSharedMemorySize, SMEM_BYTES);

    l1pen_kernel<<<GRID, THREADS, SMEM_BYTES>>>(pred, tgt, pen, nrows,
                                                (float*)d_out);
}

// round 9
// speedup vs baseline: 1.1243x; 1.0130x over previous
#include <cuda_runtime.h>
#include <cstdint>

// L1LossWithPenalty — warp-specialized TMA pipeline, 256-row tiles, 1 block/SM.
// out = (1/N) * sum_i [ sum_c |pred[i,c]-tgt[i,c]| ] * penalty[argmax pred_i, argmax tgt_i]
// N = 1048576, C = 27.  226 MB streamed -> HBM-bound.
//
// R8 vs R7 (42.5us, DRAM 70.3%):
//  - tile 128 -> 256 rows, ONE 288-thread block per SM (grid 148): per-tile
//    sync overhead amortized over 2x data, no cross-block contention.
//  - empty barrier arrive count 128 -> 8 (one arrive per consumer warp after
//    __syncwarp): kills ~120 serialized same-address shared atomics per tile.
//  - STAGES=4 (216KB smem): 3 tiles x 55.3KB = 166KB continuously in flight/SM.

#define C        27
#define ROWS     256                  // rows per tile
#define CONS     256                  // consumer threads (8 warps, 1 row each)
#define THREADS  288                  // + 1 producer warp
#define TILE_F   (ROWS * C)           // 6912 floats per array per tile
#define TILE_B   (TILE_F * 4)         // 27648 bytes per array per tile
#define CHUNK_B  (TILE_B / 2)         // 13824-byte bulk copies (safe size)
#define STAGE_F  (2 * TILE_F)
#define STAGES   4
#define SMEM_BYTES (STAGES * STAGE_F * 4)   // 221184 B
#define GRID     148

__device__ double   g_acc;
__device__ unsigned g_count;

// ---- mbarrier / TMA-bulk primitives ----
#define MBARRIER_INIT(addr, cnt) \
    asm volatile("mbarrier.init.shared.b64 [%0], %1;" :: "r"(addr), "r"(cnt) : "memory")

#define MBARRIER_ARRIVE(addr) \
    asm volatile("mbarrier.arrive.release.cta.shared.b64 _, [%0];" :: "r"(addr) : "memory")

#define MBARRIER_EXPECT_TX(addr, bytes) \
    asm volatile("mbarrier.arrive.expect_tx.shared.b64 _, [%0], %1;" \
                 :: "r"(addr), "r"(bytes) : "memory")

#define MBARRIER_WAIT_PARITY(addr, parity) do {                                   \
    uint32_t _mbar = (addr); uint32_t _par = (parity); uint32_t _done;            \
    asm volatile("{\n\t.reg .pred p;\n\t"                                         \
        "mbarrier.try_wait.parity.acquire.cta.shared::cta.b64 p, [%1], %2;\n\t"   \
        "selp.b32 %0, 1, 0, p;\n\t}"                                              \
        : "=r"(_done) : "r"(_mbar), "r"(_par) : "memory");                        \
    if (!_done) {                                                                 \
        asm volatile("{\n\t.reg .pred P1;\n\t"                                    \
            "WL_%=:\n\t"                                                          \
            "mbarrier.try_wait.parity.acquire.cta.shared::cta.b64 P1, [%0], %1, 0x989680;\n\t" \
            "@P1 bra.uni WD_%=;\n\t"                                              \
            "bra.uni WL_%=;\n\t"                                                  \
            "WD_%=:\n\t}" :: "r"(_mbar), "r"(_par) : "memory");                   \
    }                                                                             \
} while (0)

#define MBARRIER_WAIT_PARITY_RELAXED(addr, parity) do {                           \
    uint32_t _mbar = (addr); uint32_t _par = (parity); uint32_t _done;            \
    asm volatile("{\n\t.reg .pred p;\n\t"                                         \
        "mbarrier.try_wait.parity.relaxed.cta.shared::cta.b64 p, [%1], %2, 0x989680;\n\t" \
        "selp.b32 %0, 1, 0, p;\n\t}"                                              \
        : "=r"(_done) : "r"(_mbar), "r"(_par) : "memory");                        \
    if (!_done) {                                                                 \
        asm volatile("{\n\t.reg .pred P1;\n\t"                                    \
            "WL_%=:\n\t"                                                          \
            "mbarrier.try_wait.parity.relaxed.cta.shared::cta.b64 P1, [%0], %1, 0x989680;\n\t" \
            "@P1 bra.uni WD_%=;\n\t"                                              \
            "bra.uni WL_%=;\n\t"                                                  \
            "WD_%=:\n\t}" :: "r"(_mbar), "r"(_par) : "memory");                   \
    }                                                                             \
} while (0)

__device__ __forceinline__ void tma_bulk_g2s(uint32_t smem_dst, const void* gmem_src,
                                             uint32_t bytes, uint32_t mbar) {
    asm volatile(
        "cp.async.bulk.shared::cluster.global.mbarrier::complete_tx::bytes "
        "[%0], [%1], %2, [%3];"
        :: "r"(smem_dst), "l"(gmem_src), "r"(bytes), "r"(mbar) : "memory");
}

__global__ __launch_bounds__(THREADS)
void l1pen_kernel(const float* __restrict__ pred,
                  const float* __restrict__ tgt,
                  const float* __restrict__ pen,
                  int nrows,
                  float* __restrict__ out)
{
    extern __shared__ float dynsm[];            // [STAGES][2][TILE_F]
    __shared__ alignas(16) unsigned long long mbars[2 * STAGES]; // full/empty pairs
    __shared__ float s_warp[CONS / 32];

    const int tid    = threadIdx.x;
    const int wid    = tid >> 5;
    const int nfull  = nrows / ROWS;            // 4096 full tiles for N=1M
    const int ntiles = (nrows + ROWS - 1) / ROWS;
    const int stride = gridDim.x;

    const uint32_t mb0 = (uint32_t)__cvta_generic_to_shared(mbars);
    auto full_addr  = [&](int s) { return mb0 + (uint32_t)(2 * s) * 8u; };
    auto empty_addr = [&](int s) { return mb0 + (uint32_t)(2 * s + 1) * 8u; };

    if (tid == 0) {
        #pragma unroll
        for (int s = 0; s < STAGES; s++) {
            MBARRIER_INIT(full_addr(s), 1u);               // producer expect_tx arrive
            MBARRIER_INIT(empty_addr(s), (uint32_t)(CONS / 32)); // 1 arrive per consumer warp
        }
    }
    __syncthreads();

    float acc = 0.0f;

    if (wid == CONS / 32) {
        // -------- producer warp (lane 0 only) --------
        if ((tid & 31) == 0) {
            int s = 0, phase = 1;                // phase=1: first empty-wait passes
            for (int tile = blockIdx.x; tile < nfull; tile += stride) {
                MBARRIER_WAIT_PARITY_RELAXED(empty_addr(s), phase);
                MBARRIER_EXPECT_TX(full_addr(s), 2u * TILE_B);
                const uint32_t dst =
                    (uint32_t)__cvta_generic_to_shared(dynsm + s * STAGE_F);
                const char* psrc = (const char*)(pred + (long)tile * TILE_F);
                const char* tsrc = (const char*)(tgt  + (long)tile * TILE_F);
                tma_bulk_g2s(dst,                       psrc,           CHUNK_B, full_addr(s));
                tma_bulk_g2s(dst + CHUNK_B,             psrc + CHUNK_B, CHUNK_B, full_addr(s));
                tma_bulk_g2s(dst + TILE_B,              tsrc,           CHUNK_B, full_addr(s));
                tma_bulk_g2s(dst + TILE_B + CHUNK_B,    tsrc + CHUNK_B, CHUNK_B, full_addr(s));
                if (++s == STAGES) { s = 0; phase ^= 1; }
            }
        }
    } else {
        // -------- consumer warps (256 threads, 1 row each per tile) --------
        int s = 0, phase = 0;
        for (int tile = blockIdx.x; tile < ntiles; tile += stride) {
            if (tile < nfull) {
                MBARRIER_WAIT_PARITY(full_addr(s), phase);   // acquire: TMA data visible
                const float* __restrict__ pr = dynsm + s * STAGE_F + tid * C;
                const float* __restrict__ tr = pr + TILE_F;
                float l1 = 0.0f;
                float pmax = pr[0], tmax = tr[0];
                int   pidx = 0,     tidx = 0;
                #pragma unroll
                for (int c = 0; c < C; c++) {
                    float a = pr[c];
                    float b = tr[c];
                    l1 += fabsf(a - b);
                    if (a > pmax) { pmax = a; pidx = c; }   // strict > == jnp.argmax ties
                    if (b > tmax) { tmax = b; tidx = c; }
                }
                acc += l1 * __ldg(&pen[pidx * C + tidx]);
                __syncwarp();                                // all lanes' reads done
                if ((tid & 31) == 0)
                    MBARRIER_ARRIVE(empty_addr(s));          // release, 1 per warp
                if (++s == STAGES) { s = 0; phase ^= 1; }
            } else {
                // ragged last tile (dead for N=1M): direct global reads
                const int rows = nrows - nfull * ROWS;
                if (tid < rows) {
                    const long base = (long)(nfull * ROWS + tid) * C;
                    float l1 = 0.0f;
                    float pmax = pred[base], tmax = tgt[base];
                    int   pidx = 0,          tidx = 0;
                    #pragma unroll
                    for (int c = 0; c < C; c++) {
                        float a = pred[base + c];
                        float b = tgt [base + c];
                        l1 += fabsf(a - b);
                        if (a > pmax) { pmax = a; pidx = c; }
                        if (b > tmax) { tmax = b; tidx = c; }
                    }
                    acc += l1 * __ldg(&pen[pidx * C + tidx]);
                }
            }
        }

        // warp reduce (consumer warps only)
        #pragma unroll
        for (int off = 16; off > 0; off >>= 1)
            acc += __shfl_down_sync(0xffffffffu, acc, off);
        if ((tid & 31) == 0)
            s_warp[wid] = acc;
    }

    __syncthreads();   // all 9 warps: consumers done writing s_warp

    if (tid == 0) {
        float s = 0.0f;
        #pragma unroll
        for (int w = 0; w < CONS / 32; w++)
            s += s_warp[w];

        atomicAdd(&g_acc, (double)s);
        __threadfence();
        unsigned done = atomicAdd(&g_count, 1u) + 1u;
        if (done == gridDim.x) {
            __threadfence();
            double v = atomicAdd(&g_acc, 0.0);
            *out = (float)(v / (double)nrows);
            g_acc = 0.0;              // self-reset for next graph replay
            __threadfence();
            g_count = 0u;
        }
    }
}

extern "C" void kernel_launch(void* const* d_in, const int* in_sizes, int n_in,
                              void* d_out, int out_size)
{
    int pen_i = -1;
    for (int i = 0; i < n_in; i++)
        if (in_sizes[i] == C * C) { pen_i = i; break; }
    int big[2], nb = 0;
    for (int i = 0; i < n_in && nb < 2; i++)
        if (i != pen_i) big[nb++] = i;

    const float* pred = (const float*)d_in[big[0]];
    const float* tgt  = (const float*)d_in[big[1]];
    const float* pen  = (const float*)d_in[pen_i];

    const int nrows = in_sizes[big[0]] / C;

    cudaFuncSetAttribute(l1pen_kernel,
                         cudaFuncAttributeMaxDynamicSharedMemorySize, SMEM_BYTES);

    l1pen_kernel<<<GRID, THREADS, SMEM_BYTES>>>(pred, tgt, pen, nrows,
                                                (float*)d_out);
}